// round 6
// baseline (speedup 1.0000x reference)
#include <cuda_runtime.h>

// StructuredPruningIF: integrate-and-fire over T=4 timesteps.
//   mem = 0.5*thre; for t in 0..3: mem += x[t]; spike = (mem>=thre)?thre:0; mem -= spike
// Pure streaming: 256MB read + 256MB write, irreducible traffic. HBM-bound.
//
// R6: R1 config (best measured: 74.6us kernel, 6.49TB/s) with the one
// untested store policy: __stwt (write-through). Keeps L2 read-only so
// dirty-line evictions don't interleave extra turnarounds into the read
// stream at the HBM controller.
// Experiment ledger:
//   R1 plain:                    74.6us kernel, 6.49 TB/s  <- best
//   R2 __ldcs/__stcs + MLP8:     75.4us, neutral, occ hurt
//   R3 persistent grid-stride:   80.7us REGRESSED (MLP drop)
//   R4 __stcs stores:            75.8us neutral
//   R5 plain (confirm):          75.4us, 6.43 TB/s
// All flat variants sit in the 74.6-75.8us run-to-run band = memory ceiling.

#define T_STEPS 4

__global__ __launch_bounds__(256) void if_kernel(
    const float4* __restrict__ x,
    const float* __restrict__ thresh,
    float4* __restrict__ out,
    int n4)          // spatial float4 count per timestep (== timestep stride)
{
    int i = blockIdx.x * blockDim.x + threadIdx.x;
    if (i >= n4) return;

    const float thre = __ldg(thresh);
    const long s = n4;

    // Front-batched independent loads (MLP=4), first in program order.
    float4 x0 = x[0 * s + i];
    float4 x1 = x[1 * s + i];
    float4 x2 = x[2 * s + i];
    float4 x3 = x[3 * s + i];

    float4 xts[T_STEPS] = {x0, x1, x2, x3};
    const float half_thre = 0.5f * thre;
    float4 mem = make_float4(half_thre, half_thre, half_thre, half_thre);

#pragma unroll
    for (int t = 0; t < T_STEPS; t++) {
        float4 xt = xts[t];
        float4 spike;

        mem.x += xt.x; spike.x = (mem.x >= thre) ? thre : 0.0f; mem.x -= spike.x;
        mem.y += xt.y; spike.y = (mem.y >= thre) ? thre : 0.0f; mem.y -= spike.y;
        mem.z += xt.z; spike.z = (mem.z >= thre) ? thre : 0.0f; mem.z -= spike.z;
        mem.w += xt.w; spike.w = (mem.w >= thre) ? thre : 0.0f; mem.w -= spike.w;

        __stwt(&out[t * s + i], spike);   // write-through: keep L2 clean
    }
}

extern "C" void kernel_launch(void* const* d_in, const int* in_sizes, int n_in,
                              void* d_out, int out_size) {
    const float* x      = (const float*)d_in[0];   // [512,128,32,32] fp32
    const float* thresh = (const float*)d_in[1];   // [1] fp32
    float* out          = (float*)d_out;

    int total = in_sizes[0];            // 67,108,864
    int per_t = total / T_STEPS;        // 16,777,216
    int n4 = per_t / 4;                 // 4,194,304 float4 lanes

    int threads = 256;
    int blocks = (n4 + threads - 1) / threads;   // 16384
    if_kernel<<<blocks, threads>>>((const float4*)x, thresh, (float4*)out, n4);
}

// round 7
// speedup vs baseline: 1.0027x; 1.0027x over previous
#include <cuda_runtime.h>

// StructuredPruningIF: integrate-and-fire over T=4 timesteps.
//   mem = 0.5*thre; for t in 0..3: mem += x[t]; spike = (mem>=thre)?thre:0; mem -= spike
// Pure streaming: 256MB read + 256MB write, irreducible traffic. HBM-bound.
//
// FINAL: flat one-shot launch, one float4 lane/thread, front-batched MLP=4
// timestep loads, plain loads/stores, 32 regs, block=256, grid=16384.
// Measured 6.4-6.5 TB/s (~81% of 8TB/s spec) = the HBM ceiling for a
// balanced 50/50 read/write stream on this part.
//
// Experiment ledger (all on GB300 sm_103a):
//   R1 plain flat:               74.6us kernel / 82.0us dur, 6.49 TB/s  <- FINAL
//   R2 __ldcs/__stcs + MLP8:     75.4us, neutral BW, occ 79->49%
//   R3 persistent grid-stride:   80.7us REGRESSED (loop-carried loads ->
//                                sustained-MLP drop, 6.0 TB/s). Flat launch
//                                with front-batched loads wins for streaming.
//   R4 __stcs stores:            75.8us neutral
//   R5 plain (confirm):          75.4us / 82.0us dur, 6.43 TB/s
//   R6 __stwt stores:            74.3us / 82.3us dur, 6.52 TB/s (noise)
// Store/load cache policies are fully enumerated: all within +/-2% noise.
// Compute pipes <10%, issue 14% -> no non-memory lever exists.

#define T_STEPS 4

__global__ __launch_bounds__(256) void if_kernel(
    const float4* __restrict__ x,
    const float* __restrict__ thresh,
    float4* __restrict__ out,
    int n4)          // spatial float4 count per timestep (== timestep stride)
{
    int i = blockIdx.x * blockDim.x + threadIdx.x;
    if (i >= n4) return;

    const float thre = __ldg(thresh);
    const long s = n4;

    // Front-batched independent loads (MLP=4), first in program order so
    // every CTA fills the L1tex queue immediately at launch.
    float4 x0 = x[0 * s + i];
    float4 x1 = x[1 * s + i];
    float4 x2 = x[2 * s + i];
    float4 x3 = x[3 * s + i];

    float4 xts[T_STEPS] = {x0, x1, x2, x3};
    const float half_thre = 0.5f * thre;
    float4 mem = make_float4(half_thre, half_thre, half_thre, half_thre);

#pragma unroll
    for (int t = 0; t < T_STEPS; t++) {
        float4 xt = xts[t];
        float4 spike;

        mem.x += xt.x; spike.x = (mem.x >= thre) ? thre : 0.0f; mem.x -= spike.x;
        mem.y += xt.y; spike.y = (mem.y >= thre) ? thre : 0.0f; mem.y -= spike.y;
        mem.z += xt.z; spike.z = (mem.z >= thre) ? thre : 0.0f; mem.z -= spike.z;
        mem.w += xt.w; spike.w = (mem.w >= thre) ? thre : 0.0f; mem.w -= spike.w;

        out[t * s + i] = spike;
    }
}

extern "C" void kernel_launch(void* const* d_in, const int* in_sizes, int n_in,
                              void* d_out, int out_size) {
    const float* x      = (const float*)d_in[0];   // [512,128,32,32] fp32
    const float* thresh = (const float*)d_in[1];   // [1] fp32
    float* out          = (float*)d_out;

    int total = in_sizes[0];            // 67,108,864
    int per_t = total / T_STEPS;        // 16,777,216
    int n4 = per_t / 4;                 // 4,194,304 float4 lanes

    int threads = 256;
    int blocks = (n4 + threads - 1) / threads;   // 16384
    if_kernel<<<blocks, threads>>>((const float4*)x, thresh, (float4*)out, n4);
}

// round 8
// speedup vs baseline: 1.0039x; 1.0012x over previous
#include <cuda_runtime.h>

// StructuredPruningIF: integrate-and-fire over T=4 timesteps.
//   mem = 0.5*thre; for t in 0..3: mem += x[t]; spike = (mem>=thre)?thre:0; mem -= spike
// Pure streaming: 256MB read + 256MB write, irreducible. HBM-bound at ~81%.
//
// R8: identical body to the FINAL config; single-variable change block
// 256 -> 128 (grid 16384 -> 32768). Finer CTA granularity halves the
// per-CTA front-batched load burst, probing the cross-CTA L1tex-queue
// spread term (oe*MLP_p1 > Q_th regime) and wave-tail imbalance.
//
// Ledger: R1/R5/R7 plain-256: 74.6/75.4/75.2us kernel, 6.43-6.49 TB/s.
//   R2 ldcs/stcs+MLP8 neutral; R3 persistent REGRESSED; R4 stcs neutral;
//   R6 stwt neutral (74.3us, noise). All policies enumerated.

#define T_STEPS 4

__global__ __launch_bounds__(128) void if_kernel(
    const float4* __restrict__ x,
    const float* __restrict__ thresh,
    float4* __restrict__ out,
    int n4)          // spatial float4 count per timestep (== timestep stride)
{
    int i = blockIdx.x * blockDim.x + threadIdx.x;
    if (i >= n4) return;

    const float thre = __ldg(thresh);
    const long s = n4;

    // Front-batched independent loads (MLP=4), first in program order.
    float4 x0 = x[0 * s + i];
    float4 x1 = x[1 * s + i];
    float4 x2 = x[2 * s + i];
    float4 x3 = x[3 * s + i];

    float4 xts[T_STEPS] = {x0, x1, x2, x3};
    const float half_thre = 0.5f * thre;
    float4 mem = make_float4(half_thre, half_thre, half_thre, half_thre);

#pragma unroll
    for (int t = 0; t < T_STEPS; t++) {
        float4 xt = xts[t];
        float4 spike;

        mem.x += xt.x; spike.x = (mem.x >= thre) ? thre : 0.0f; mem.x -= spike.x;
        mem.y += xt.y; spike.y = (mem.y >= thre) ? thre : 0.0f; mem.y -= spike.y;
        mem.z += xt.z; spike.z = (mem.z >= thre) ? thre : 0.0f; mem.z -= spike.z;
        mem.w += xt.w; spike.w = (mem.w >= thre) ? thre : 0.0f; mem.w -= spike.w;

        out[t * s + i] = spike;
    }
}

extern "C" void kernel_launch(void* const* d_in, const int* in_sizes, int n_in,
                              void* d_out, int out_size) {
    const float* x      = (const float*)d_in[0];   // [512,128,32,32] fp32
    const float* thresh = (const float*)d_in[1];   // [1] fp32
    float* out          = (float*)d_out;

    int total = in_sizes[0];            // 67,108,864
    int per_t = total / T_STEPS;        // 16,777,216
    int n4 = per_t / 4;                 // 4,194,304 float4 lanes

    int threads = 128;
    int blocks = (n4 + threads - 1) / threads;   // 32768
    if_kernel<<<blocks, threads>>>((const float4*)x, thresh, (float4*)out, n4);
}

// round 9
// speedup vs baseline: 1.0043x; 1.0004x over previous
#include <cuda_runtime.h>

// StructuredPruningIF: integrate-and-fire over T=4 timesteps.
//   mem = 0.5*thre; for t in 0..3: mem += x[t]; spike = (mem>=thre)?thre:0; mem -= spike
// Pure streaming: 256MB read + 256MB write, irreducible traffic. HBM-bound.
//
// FINAL CONFIG (R8): flat one-shot launch, one float4 lane/thread,
// front-batched MLP=4 timestep loads, plain loads/stores, 32 regs,
// block=128, grid=32768. Measured 74.4us kernel / 6.52 TB/s (81.5% of
// 8 TB/s spec) — the empirical HBM ceiling for a balanced 50/50 R/W
// stream on GB300.
//
// Full experiment ledger (GB300 sm_103a, 8 rounds):
//   R1 plain flat b256:        74.6us kernel / 82.0us dur, 6.49 TB/s
//   R2 __ldcs/__stcs + MLP8:   75.4us, neutral BW, occ 79->49% (48 regs)
//   R3 persistent grid-stride: 80.7us REGRESSED — loop-carried loads sit
//      behind prior stores, sustained-MLP drops (6.0 TB/s). For saturated
//      streaming, flat launches with front-batched loads win.
//   R4 __stcs stores:          75.8us neutral
//   R5 plain b256 (confirm):   75.4us, 6.43 TB/s
//   R6 __stwt stores:          74.3us, 6.52 TB/s (within noise)
//   R7 plain b256 (confirm):   75.2us, 6.44 TB/s
//   R8 plain b128:             74.4us / 82.0us dur, 6.52 TB/s, DRAM 82.3%  <- FINAL
// Cache policy (WB/evict-first/write-through), MLP depth (4/8), launch
// structure (flat/persistent), block size (128/256): all enumerated.
// Everything except R3 sits in the +/-2% run-to-run band = the floor.
// Compute pipes <10%, issue 14% -> no non-memory lever exists.

#define T_STEPS 4

__global__ __launch_bounds__(128) void if_kernel(
    const float4* __restrict__ x,
    const float* __restrict__ thresh,
    float4* __restrict__ out,
    int n4)          // spatial float4 count per timestep (== timestep stride)
{
    int i = blockIdx.x * blockDim.x + threadIdx.x;
    if (i >= n4) return;

    const float thre = __ldg(thresh);
    const long s = n4;

    // Front-batched independent loads (MLP=4), first in program order so
    // every CTA fills the L1tex queue immediately at launch.
    float4 x0 = x[0 * s + i];
    float4 x1 = x[1 * s + i];
    float4 x2 = x[2 * s + i];
    float4 x3 = x[3 * s + i];

    float4 xts[T_STEPS] = {x0, x1, x2, x3};
    const float half_thre = 0.5f * thre;
    float4 mem = make_float4(half_thre, half_thre, half_thre, half_thre);

#pragma unroll
    for (int t = 0; t < T_STEPS; t++) {
        float4 xt = xts[t];
        float4 spike;

        mem.x += xt.x; spike.x = (mem.x >= thre) ? thre : 0.0f; mem.x -= spike.x;
        mem.y += xt.y; spike.y = (mem.y >= thre) ? thre : 0.0f; mem.y -= spike.y;
        mem.z += xt.z; spike.z = (mem.z >= thre) ? thre : 0.0f; mem.z -= spike.z;
        mem.w += xt.w; spike.w = (mem.w >= thre) ? thre : 0.0f; mem.w -= spike.w;

        out[t * s + i] = spike;
    }
}

extern "C" void kernel_launch(void* const* d_in, const int* in_sizes, int n_in,
                              void* d_out, int out_size) {
    const float* x      = (const float*)d_in[0];   // [512,128,32,32] fp32
    const float* thresh = (const float*)d_in[1];   // [1] fp32
    float* out          = (float*)d_out;

    int total = in_sizes[0];            // 67,108,864
    int per_t = total / T_STEPS;        // 16,777,216
    int n4 = per_t / 4;                 // 4,194,304 float4 lanes

    int threads = 128;
    int blocks = (n4 + threads - 1) / threads;   // 32768
    if_kernel<<<blocks, threads>>>((const float4*)x, thresh, (float4*)out, n4);
}